// round 1
// baseline (speedup 1.0000x reference)
#include <cuda_runtime.h>

// ---------------------------------------------------------------------------
// WT series decomposition: 4-level DWT lowpass analysis + synthesis of trend,
// season = x - trend. One CTA per (batch, channel) row; everything in SMEM.
//
// Analysis (stride-2 correlation, zero pad):
//   y[n] = sum_{k=0..7} x[2n+k-6] * DEC_LO[7-k]
// Stage lengths: 32768 -> 16387 -> 8197 -> 4102 -> 2054
//
// Synthesis (transposed conv, lhs_dilation=2, pad (1,1), cross-correlation):
//   t[2q]   = sum_j lo[q+j]*DEC_LO[2j+1]
//   t[2q+1] = sum_j lo[q+j]*DEC_LO[2j]
// Stage lengths (with [:-1] trims): 2054->4102, 4102->8198, (8197)->16388,
// (16387)->32768. Max read index is n_in-1 at every stage: no bounds checks.
// ---------------------------------------------------------------------------

#define THREADS 1024

#define ROW_N   32768
#define N1      16387
#define N2      8197
#define N3      4102
#define N4      2054

// DEC_LO coefficients
#define D0 (-0.010597401784997278f)
#define D1 ( 0.032883011666982945f)
#define D2 ( 0.030841381835986965f)
#define D3 (-0.18703481171888114f)
#define D4 (-0.02798376941698385f)
#define D5 ( 0.6308807679295904f)
#define D6 ( 0.7148465705525415f)
#define D7 ( 0.23037781330885523f)

// SMEM layout (floats): x[32768] | B0[16388] | B1[8198]
#define B0_OFF  ROW_N
#define B1_OFF  (ROW_N + 16388)
#define SMEM_FLOATS (ROW_N + 16388 + 8198)
#define SMEM_BYTES  (SMEM_FLOATS * 4)

static __device__ __forceinline__ void afb_stage(const float* __restrict__ in, int n_in,
                                                 float* __restrict__ out, int n_out) {
    // h[k] = DEC_LO[7-k]
    for (int i = threadIdx.x; i < n_out; i += THREADS) {
        const int base = 2 * i - 6;
        float acc;
        if (base >= 0 && base + 7 < n_in) {
            acc =      in[base + 0] * D7;
            acc = fmaf(in[base + 1],  D6, acc);
            acc = fmaf(in[base + 2],  D5, acc);
            acc = fmaf(in[base + 3],  D4, acc);
            acc = fmaf(in[base + 4],  D3, acc);
            acc = fmaf(in[base + 5],  D2, acc);
            acc = fmaf(in[base + 6],  D1, acc);
            acc = fmaf(in[base + 7],  D0, acc);
        } else {
            const float hh[8] = {D7, D6, D5, D4, D3, D2, D1, D0};
            acc = 0.0f;
            #pragma unroll
            for (int k = 0; k < 8; ++k) {
                const int j = base + k;
                if (j >= 0 && j < n_in) acc = fmaf(in[j], hh[k], acc);
            }
        }
        out[i] = acc;
    }
}

// n_pairs = n_out / 2; out[2q], out[2q+1] from in[q..q+3]. No bounds checks
// needed (proved: max index read = n_in_effective - 1 for every stage).
static __device__ __forceinline__ void sfb_stage(const float* __restrict__ in,
                                                 float* __restrict__ out, int n_pairs) {
    for (int q = threadIdx.x; q < n_pairs; q += THREADS) {
        const float a = in[q], b = in[q + 1], c = in[q + 2], d = in[q + 3];
        float te =      a * D1;          // even output
        te = fmaf(b, D3, te);
        te = fmaf(c, D5, te);
        te = fmaf(d, D7, te);
        float to =      a * D0;          // odd output
        to = fmaf(b, D2, to);
        to = fmaf(c, D4, to);
        to = fmaf(d, D6, to);
        *reinterpret_cast<float2*>(out + 2 * q) = make_float2(te, to);
    }
}

__global__ __launch_bounds__(THREADS, 1)
void wt_decomp_kernel(const float* __restrict__ x,
                      float* __restrict__ season,
                      float* __restrict__ trend) {
    extern __shared__ float smem[];
    float* sx = smem;
    float* B0 = smem + B0_OFF;
    float* B1 = smem + B1_OFF;

    const size_t off = (size_t)blockIdx.x * ROW_N;

    // Load row into SMEM (float4 vectorized)
    {
        const float4* xg4 = reinterpret_cast<const float4*>(x + off);
        float4* sx4 = reinterpret_cast<float4*>(sx);
        #pragma unroll 2
        for (int i = threadIdx.x; i < ROW_N / 4; i += THREADS) sx4[i] = xg4[i];
    }
    __syncthreads();

    // Analysis chain (lowpass only; details are unused by the reference)
    afb_stage(sx, ROW_N, B0, N1); __syncthreads();
    afb_stage(B0, N1,   B1, N2); __syncthreads();
    afb_stage(B1, N2,   B0, N3); __syncthreads();
    afb_stage(B0, N3,   B1, N4); __syncthreads();

    // Synthesis chain
    sfb_stage(B1, B0, N3 / 2);        __syncthreads();   // 2054  -> 4102  (B0)
    sfb_stage(B0, B1, 8198 / 2);      __syncthreads();   // 4102  -> 8198  (B1)
    sfb_stage(B1, B0, 16388 / 2);     __syncthreads();   // 8197* -> 16388 (B0)  (*trim)

    // Final stage: 16387* -> 32768, fused with season = x - trend, direct to GMEM
    float* tre = trend + off;
    float* sea = season + off;
    for (int q = threadIdx.x; q < ROW_N / 2; q += THREADS) {
        const float a = B0[q], b = B0[q + 1], c = B0[q + 2], d = B0[q + 3];
        float te =      a * D1;
        te = fmaf(b, D3, te);
        te = fmaf(c, D5, te);
        te = fmaf(d, D7, te);
        float to =      a * D0;
        to = fmaf(b, D2, to);
        to = fmaf(c, D4, to);
        to = fmaf(d, D6, to);
        const float2 xv = *reinterpret_cast<const float2*>(sx + 2 * q);
        *reinterpret_cast<float2*>(tre + 2 * q) = make_float2(te, to);
        *reinterpret_cast<float2*>(sea + 2 * q) = make_float2(xv.x - te, xv.y - to);
    }
}

extern "C" void kernel_launch(void* const* d_in, const int* in_sizes, int n_in,
                              void* d_out, int out_size) {
    (void)n_in; (void)out_size;
    const float* x = (const float*)d_in[0];
    float* out = (float*)d_out;

    const int nsig = in_sizes[0] / ROW_N;          // 512 for the bench shape
    const size_t total = (size_t)nsig * ROW_N;
    float* season = out;                            // tuple order: (season, trend)
    float* trend  = out + total;

    cudaFuncSetAttribute(wt_decomp_kernel,
                         cudaFuncAttributeMaxDynamicSharedMemorySize, SMEM_BYTES);
    wt_decomp_kernel<<<nsig, THREADS, SMEM_BYTES>>>(x, season, trend);
}